// round 3
// baseline (speedup 1.0000x reference)
#include <cuda_runtime.h>

// Who2com reduces algebraically to mean over the N (agent) axis:
//   out[b,c,h,w] = (1/N) * sum_n bevs[b,n,c,h,w]
// (softmax columns sum to 1; val_mat is broadcast over the key axis).
//
// B=32, N=5, C=256, H=W=16.
// 256-bit (v8.f32) loads/stores: each (b,n) slice = 256KiB = 8192 x 32B.
// Output = 32 * 8192 = 262144 x 32B elements. One per thread.
// Grid: 2048 blocks x 128 threads (exact, no tail).

static constexpr int B_    = 32;
static constexpr int N_    = 5;
static constexpr int CHW8  = 256 * 16 * 16 / 8;   // 8192 v8-elems per (b,n) slice
static constexpr int OUT8  = B_ * CHW8;           // 262144
static constexpr int THREADS = 128;
static constexpr int NBLOCKS = OUT8 / THREADS;    // 2048

struct alignas(32) f32x8 { float v[8]; };

__device__ __forceinline__ f32x8 ldg256(const f32x8* p) {
    f32x8 r;
    asm volatile("ld.global.nc.v8.f32 {%0,%1,%2,%3,%4,%5,%6,%7}, [%8];"
                 : "=f"(r.v[0]), "=f"(r.v[1]), "=f"(r.v[2]), "=f"(r.v[3]),
                   "=f"(r.v[4]), "=f"(r.v[5]), "=f"(r.v[6]), "=f"(r.v[7])
                 : "l"(p));
    return r;
}

__device__ __forceinline__ void stg256(f32x8* p, const f32x8& r) {
    asm volatile("st.global.cs.v8.f32 [%0], {%1,%2,%3,%4,%5,%6,%7,%8};"
                 :: "l"(p),
                    "f"(r.v[0]), "f"(r.v[1]), "f"(r.v[2]), "f"(r.v[3]),
                    "f"(r.v[4]), "f"(r.v[5]), "f"(r.v[6]), "f"(r.v[7])
                 : "memory");
}

__global__ __launch_bounds__(THREADS) void who2com_mean_kernel(
    const f32x8* __restrict__ bevs, f32x8* __restrict__ out)
{
    int idx = blockIdx.x * THREADS + threadIdx.x;  // 0 .. OUT8-1, exact
    int b   = idx >> 13;                           // / CHW8
    int chw = idx & (CHW8 - 1);                    // % CHW8

    const f32x8* base = bevs + (size_t)b * N_ * CHW8 + chw;

    f32x8 a0 = ldg256(base + 0 * CHW8);
    f32x8 a1 = ldg256(base + 1 * CHW8);
    f32x8 a2 = ldg256(base + 2 * CHW8);
    f32x8 a3 = ldg256(base + 3 * CHW8);
    f32x8 a4 = ldg256(base + 4 * CHW8);

    const float inv_n = 0.2f;
    f32x8 r;
#pragma unroll
    for (int i = 0; i < 8; i++)
        r.v[i] = (a0.v[i] + a1.v[i] + a2.v[i] + a3.v[i] + a4.v[i]) * inv_n;

    stg256(out + idx, r);
}

extern "C" void kernel_launch(void* const* d_in, const int* in_sizes, int n_in,
                              void* d_out, int out_size)
{
    const f32x8* bevs = (const f32x8*)d_in[0];  // (B, N, C, H, W) fp32
    f32x8* out = (f32x8*)d_out;                 // (B, C, H, W) fp32
    who2com_mean_kernel<<<NBLOCKS, THREADS>>>(bevs, out);
}